// round 2
// baseline (speedup 1.0000x reference)
#include <cuda_runtime.h>
#include <cuda_bf16.h>

// LocalFeatureAggregation: B=4, N=16384, K=16, C=64, D=64
// out[p, 0:64]   = mean_k leaky( geom[p,k,:] @ w^T + b )
// out[p, 64:128] = mean_k features[b, idx[p,k], :]
//
// One warp per point. Lane l owns MLP channels {l, l+32} as a packed f32x2
// pair, and gather channels {2l, 2l+1} as a packed f32x2 pair.
// NOTE: neighbor_indices is int32 on device (JAX downgrades int64 w/o x64).

#define KNB 16

__device__ __forceinline__ unsigned long long pk2(float x, float y) {
    unsigned long long r;
    asm("mov.b64 %0, {%1,%2};" : "=l"(r) : "f"(x), "f"(y));
    return r;
}
__device__ __forceinline__ void upk2(unsigned long long v, float& x, float& y) {
    asm("mov.b64 {%0,%1}, %2;" : "=f"(x), "=f"(y) : "l"(v));
}
__device__ __forceinline__ unsigned long long fma2(unsigned long long a,
                                                   unsigned long long b,
                                                   unsigned long long c) {
    unsigned long long d;
    asm("fma.rn.f32x2 %0, %1, %2, %3;" : "=l"(d) : "l"(a), "l"(b), "l"(c));
    return d;
}
__device__ __forceinline__ unsigned long long add2(unsigned long long a,
                                                   unsigned long long b) {
    unsigned long long d;
    asm("add.rn.f32x2 %0, %1, %2;" : "=l"(d) : "l"(a), "l"(b));
    return d;
}
__device__ __forceinline__ unsigned long long mul2(unsigned long long a,
                                                   unsigned long long b) {
    unsigned long long d;
    asm("mul.rn.f32x2 %0, %1, %2;" : "=l"(d) : "l"(a), "l"(b));
    return d;
}

__global__ __launch_bounds__(256) void lfa_kernel(
    const float* __restrict__ features,       // [B, N, 64]
    const float* __restrict__ geom,           // [B, N, 16, 4]
    const float* __restrict__ w,              // [64, 4]
    const float* __restrict__ bias,           // [64]
    const int* __restrict__ nbr,              // [B, N, 16] int32
    float* __restrict__ out,                  // [B, N, 128]
    int points, int n_log2)                   // points = B*N, n_log2 = log2(N)
{
    __shared__ float4 ws[64];                         // weight rows
    __shared__ float  bs[64];                         // bias
    __shared__ unsigned long long sg[8][64];          // duplicated geom per warp: (g,g) pairs
    __shared__ int sidx[8][16];                       // neighbor indices per warp

    const int tid = threadIdx.x;
    if (tid < 64) {
        ws[tid] = ((const float4*)w)[tid];
        bs[tid] = bias[tid];
    }
    __syncthreads();

    const int warp = tid >> 5;
    const int lane = tid & 31;
    const int p = blockIdx.x * 8 + warp;              // point id
    if (p >= points) return;                          // uniform per warp

    // ---- stage geometry (duplicated into f32x2 pairs) and indices ----
    const float2 gv = ((const float2*)(geom + (size_t)p * 64))[lane];   // floats 2l,2l+1
    sg[warp][2 * lane]     = pk2(gv.x, gv.x);
    sg[warp][2 * lane + 1] = pk2(gv.y, gv.y);
    if (lane < KNB) sidx[warp][lane] = nbr[(size_t)p * KNB + lane];
    __syncwarp();

    // ---- per-lane packed weight/bias pairs (d = lane, lane+32) ----
    const float4 wA = ws[lane];
    const float4 wB = ws[lane + 32];
    const unsigned long long w0 = pk2(wA.x, wB.x);
    const unsigned long long w1 = pk2(wA.y, wB.y);
    const unsigned long long w2 = pk2(wA.z, wB.z);
    const unsigned long long w3 = pk2(wA.w, wB.w);
    const unsigned long long bp = pk2(bs[lane], bs[lane + 32]);
    const unsigned long long c055 = pk2(0.55f, 0.55f);
    const unsigned long long c045 = pk2(0.45f, 0.45f);

    const int bIdx = p >> n_log2;
    const int nPerB = 1 << n_log2;
    // gather base for this batch, as 8-byte words; lane l covers channels 2l,2l+1
    const unsigned long long* featq =
        (const unsigned long long*)(features + (size_t)bIdx * nPerB * 64);

    unsigned long long accD = 0ull;   // (+0.f, +0.f)
    unsigned long long accC = 0ull;

    const unsigned long long* g2 = &sg[warp][0];

#pragma unroll
    for (int k = 0; k < KNB; k++) {
        // MLP: t = geom[k] . w_pair + b_pair   (broadcast LDS, conflict-free)
        unsigned long long t = fma2(g2[4 * k + 0], w0, bp);
        t = fma2(g2[4 * k + 1], w1, t);
        t = fma2(g2[4 * k + 2], w2, t);
        t = fma2(g2[4 * k + 3], w3, t);
        // leaky(t) = 0.55*t + 0.45*|t|  (exact for slope 0.1)
        const unsigned long long ta = t & 0x7fffffff7fffffffULL;
        accD = fma2(t, c055, accD);
        accD = fma2(ta, c045, accD);

        // gather: coalesced 8B loads, mostly L2 hits (feature table fits in L2)
        const int nb = sidx[warp][k];
        accC = add2(accC, featq[(size_t)nb * 32 + lane]);
    }

    // ---- epilogue: mean over K, coalesced stores ----
    const unsigned long long inv = pk2(0.0625f, 0.0625f);
    accD = mul2(accD, inv);
    accC = mul2(accC, inv);

    float dA, dB, cx, cy;
    upk2(accD, dA, dB);
    upk2(accC, cx, cy);

    const size_t ob = (size_t)p * 128;
    out[ob + lane]      = dA;            // channels [0,32)
    out[ob + 32 + lane] = dB;            // channels [32,64)
    ((float2*)(out + ob + 64))[lane] = make_float2(cx, cy);   // channels [64,128)
}

extern "C" void kernel_launch(void* const* d_in, const int* in_sizes, int n_in,
                              void* d_out, int out_size) {
    const float* features    = (const float*)d_in[0];
    const float* geom        = (const float*)d_in[1];
    const float* w           = (const float*)d_in[2];
    const float* bias        = (const float*)d_in[3];
    const int*   nbr         = (const int*)d_in[4];    // int32 (JAX x64 off)
    float* out               = (float*)d_out;

    const int points = in_sizes[0] / 64;          // B*N = 65536
    const int n_log2 = 14;                        // N = 16384 per batch

    const int blocks = (points + 7) / 8;          // 8 warps/block, 1 point/warp
    (void)n_in; (void)out_size;
    lfa_kernel<<<blocks, 256>>>(features, geom, w, bias, nbr, out, points, n_log2);
}

// round 4
// speedup vs baseline: 1.0952x; 1.0952x over previous
#include <cuda_runtime.h>
#include <cuda_bf16.h>

// LocalFeatureAggregation: B=4, N=16384, K=16, C=64, D=64
// out[p, 0:64]   = mean_k leaky( geom[p,k,:] @ w^T + b )
// out[p, 64:128] = mean_k features[b, idx[p,k], :]
//
// One warp per point.
//  MLP:   lane l owns channel pair {l, l+32} packed f32x2; geometry broadcast
//         from shared as duplicated pairs via LDS.128 (2 per k).
//  Gather: lanes 0-15 handle even k, 16-31 odd k; lane loads float4 covering
//         channels 4(l&15)..+3 -> 8 LDG.128 per point; halves combined by shfl.

#define KNB 16
#define FULLMASK 0xffffffffu

__device__ __forceinline__ unsigned long long pk2(float x, float y) {
    unsigned long long r;
    asm("mov.b64 %0, {%1,%2};" : "=l"(r) : "f"(x), "f"(y));
    return r;
}
__device__ __forceinline__ void upk2(unsigned long long v, float& x, float& y) {
    asm("mov.b64 {%0,%1}, %2;" : "=f"(x), "=f"(y) : "l"(v));
}
__device__ __forceinline__ unsigned long long fma2(unsigned long long a,
                                                   unsigned long long b,
                                                   unsigned long long c) {
    unsigned long long d;
    asm("fma.rn.f32x2 %0, %1, %2, %3;" : "=l"(d) : "l"(a), "l"(b), "l"(c));
    return d;
}
__device__ __forceinline__ unsigned long long add2(unsigned long long a,
                                                   unsigned long long b) {
    unsigned long long d;
    asm("add.rn.f32x2 %0, %1, %2;" : "=l"(d) : "l"(a), "l"(b));
    return d;
}
__device__ __forceinline__ unsigned long long mul2(unsigned long long a,
                                                   unsigned long long b) {
    unsigned long long d;
    asm("mul.rn.f32x2 %0, %1, %2;" : "=l"(d) : "l"(a), "l"(b));
    return d;
}

__global__ __launch_bounds__(256) void lfa_kernel(
    const float* __restrict__ features,       // [B, N, 64]
    const float* __restrict__ geom,           // [B, N, 16, 4]
    const float* __restrict__ w,              // [64, 4]
    const float* __restrict__ bias,           // [64]
    const int* __restrict__ nbr,              // [B, N, 16] int32
    float* __restrict__ out,                  // [B, N, 128]
    int points, int n_log2)
{
    __shared__ float4 ws[64];
    __shared__ float  bs[64];
    __shared__ ulonglong2 sgd[8][32];   // duplicated geom pairs, 16B entries

    const int tid = threadIdx.x;
    if (tid < 64) {
        ws[tid] = ((const float4*)w)[tid];
        bs[tid] = bias[tid];
    }
    __syncthreads();

    const int warp = tid >> 5;
    const int lane = tid & 31;
    const int p = blockIdx.x * 8 + warp;
    if (p >= points) return;                          // uniform per warp

    // ---- stage geometry as duplicated pairs: one STS.128 per lane ----
    const float2 gv = ((const float2*)(geom + (size_t)p * 64))[lane];
    sgd[warp][lane] = make_ulonglong2(pk2(gv.x, gv.x), pk2(gv.y, gv.y));

    // ---- neighbor indices: 4 uniform (broadcast) LDG.128 ----
    const int4* nb4 = (const int4*)(nbr + (size_t)p * KNB);
    const int4 i0 = nb4[0], i1 = nb4[1], i2 = nb4[2], i3 = nb4[3];

    __syncwarp();

    // ---- per-lane packed weight/bias pairs (d = lane, lane+32) ----
    const float4 wA = ws[lane];
    const float4 wB = ws[lane + 32];
    const unsigned long long w0 = pk2(wA.x, wB.x);
    const unsigned long long w1 = pk2(wA.y, wB.y);
    const unsigned long long w2 = pk2(wA.z, wB.z);
    const unsigned long long w3 = pk2(wA.w, wB.w);
    const unsigned long long bp = pk2(bs[lane], bs[lane + 32]);
    const unsigned long long c055 = pk2(0.55f, 0.55f);
    const unsigned long long c045 = pk2(0.45f, 0.45f);

    const int bIdx = p >> n_log2;
    const int nPerB = 1 << n_log2;
    const int h = lane >> 4;            // half-warp: 0 -> even k, 1 -> odd k
    const int c = lane & 15;            // float4 slot within row
    const ulonglong2* featq =
        (const ulonglong2*)(features + (size_t)bIdx * nPerB * 64) + c;

    unsigned long long gx = 0ull, gy = 0ull;   // gather acc (ch 4c..4c+3)

    // ---- gather: 8 LDG.128, two rows per instruction ----
    // row stride: 64 floats = 256 B = 16 ulonglong2
#define GSTEP(ia, ib)                                              \
    {                                                              \
        const int r = h ? (ib) : (ia);                             \
        const ulonglong2 v = featq[(size_t)r * 16];                \
        gx = add2(gx, v.x);                                        \
        gy = add2(gy, v.y);                                        \
    }
    GSTEP(i0.x, i0.y) GSTEP(i0.z, i0.w)
    GSTEP(i1.x, i1.y) GSTEP(i1.z, i1.w)
    GSTEP(i2.x, i2.y) GSTEP(i2.z, i2.w)
    GSTEP(i3.x, i3.y) GSTEP(i3.z, i3.w)
#undef GSTEP

    // ---- MLP: 2 broadcast LDS.128 per k ----
    unsigned long long accD = 0ull;
    const ulonglong2* g2 = &sgd[warp][0];
#pragma unroll
    for (int k = 0; k < KNB; k++) {
        const ulonglong2 qa = g2[2 * k];       // (g0,g0),(g1,g1)
        const ulonglong2 qb = g2[2 * k + 1];   // (g2,g2),(g3,g3)
        unsigned long long t = fma2(qa.x, w0, bp);
        t = fma2(qa.y, w1, t);
        t = fma2(qb.x, w2, t);
        t = fma2(qb.y, w3, t);
        const unsigned long long ta = t & 0x7fffffff7fffffffULL;
        accD = fma2(t, c055, accD);
        accD = fma2(ta, c045, accD);
    }

    // ---- combine gather halves ----
    const unsigned long long ox = __shfl_down_sync(FULLMASK, gx, 16);
    const unsigned long long oy = __shfl_down_sync(FULLMASK, gy, 16);

    const unsigned long long inv = pk2(0.0625f, 0.0625f);
    accD = mul2(accD, inv);

    float dA, dB;
    upk2(accD, dA, dB);

    const size_t ob = (size_t)p * 128;
    out[ob + lane]      = dA;                 // channels [0,32)
    out[ob + 32 + lane] = dB;                 // channels [32,64)

    if (lane < 16) {
        ulonglong2 res;
        res.x = mul2(add2(gx, ox), inv);
        res.y = mul2(add2(gy, oy), inv);
        ((ulonglong2*)(out + ob + 64))[c] = res;   // channels [64,128)
    }
}

extern "C" void kernel_launch(void* const* d_in, const int* in_sizes, int n_in,
                              void* d_out, int out_size) {
    const float* features    = (const float*)d_in[0];
    const float* geom        = (const float*)d_in[1];
    const float* w           = (const float*)d_in[2];
    const float* bias        = (const float*)d_in[3];
    const int*   nbr         = (const int*)d_in[4];    // int32 (JAX x64 off)
    float* out               = (float*)d_out;

    const int points = in_sizes[0] / 64;          // B*N = 65536
    const int n_log2 = 14;                        // N = 16384 per batch

    const int blocks = (points + 7) / 8;
    (void)n_in; (void)out_size;
    lfa_kernel<<<blocks, 256>>>(features, geom, w, bias, nbr, out, points, n_log2);
}